// round 16
// baseline (speedup 1.0000x reference)
#include <cuda_runtime.h>
#include <cuda_bf16.h>
#include <math.h>

// EMA with SD, chunked parallel scan (round 15).
// x (T=8192, D=128); h_a0, h_sd0, alpha (N=32, D=128).
// out: (T, 2N, D) fp32, then hN_a (N,D), hN_sd (N,D).
//
// LTS-byte model: the binding resource is L2 transit. x(t,d) is shared by
// all N=32 state rows, so each thread now processes MULTIPLE n per x load:
//  pass1: thread = (d, 4 n's), grid (CS=128, 8) x 128thr. x traffic 128->32MB.
//         Straight 64-step loop per lane:
//           u = x - g; g += a*u; A = b*(A + a*u^2)      (exact, r6 family)
//  pass2: thread = (d, 2 n's), grid (CR=64, 16) x 128thr = 4096 warps
//         (r12's proven residency + per-block fold stagger preserved).
//         Per-block prefix fold (W=b^64):
//           hv' = W*hv + W(1-W)*ha^2 - 2W*P*ha + A ; ha' = W*ha + P
//         then exact replay with __stcs scalar streaming stores.

#define TT 8192
#define DD 128
#define NN 32
#define CS 128
#define LS 64
#define CR 64
#define LR 128
#define LANES (NN * DD)

__device__ float g_P[CS * LANES];
__device__ float g_A[CS * LANES];

__device__ __forceinline__ float sqrt_fast(float v) {
    float r;
    asm("sqrt.approx.f32 %0, %1;" : "=f"(r) : "f"(v));
    return r;
}

// ---------------------------------------------------------------- pass 1
// Block (c, g): 128 threads = d; each thread handles n = g, g+8, g+16, g+24.
__global__ __launch_bounds__(128) void ema_pass1(
    const float* __restrict__ x,
    const float* __restrict__ alpha)
{
    const int c = blockIdx.x;            // 0..CS-1
    const int g = blockIdx.y;            // 0..7
    const int d = threadIdx.x;           // 0..127

    const int n0 = g,      n1 = g + 8,  n2 = g + 16, n3 = g + 24;
    const int i0 = n0 * DD + d, i1 = n1 * DD + d, i2 = n2 * DD + d, i3 = n3 * DD + d;

    const float a0 = alpha[i0], a1 = alpha[i1], a2 = alpha[i2], a3 = alpha[i3];
    const float b0 = 1.0f - a0, b1 = 1.0f - a1, b2 = 1.0f - a2, b3 = 1.0f - a3;

    const float* xp = x + (size_t)c * LS * DD + d;

    float g0 = 0.f, g1 = 0.f, g2 = 0.f, g3 = 0.f;
    float A0 = 0.f, A1 = 0.f, A2 = 0.f, A3 = 0.f;

#pragma unroll 8
    for (int i = 0; i < LS; ++i) {
        const float xv = xp[(size_t)i * DD];   // one load feeds 4 lanes
        float u;
        u = xv - g0; g0 = fmaf(a0, u, g0); A0 = b0 * fmaf(a0, u * u, A0);
        u = xv - g1; g1 = fmaf(a1, u, g1); A1 = b1 * fmaf(a1, u * u, A1);
        u = xv - g2; g2 = fmaf(a2, u, g2); A2 = b2 * fmaf(a2, u * u, A2);
        u = xv - g3; g3 = fmaf(a3, u, g3); A3 = b3 * fmaf(a3, u * u, A3);
    }

    const int sbase = c * LANES;
    g_P[sbase + i0] = g0;  g_A[sbase + i0] = A0;
    g_P[sbase + i1] = g1;  g_A[sbase + i1] = A1;
    g_P[sbase + i2] = g2;  g_A[sbase + i2] = A2;
    g_P[sbase + i3] = g3;  g_A[sbase + i3] = A3;
}

// ---------------------------------------------------------------- pass 2
// Block (c, g): 128 threads = d; each thread handles n = g and n = g+16.
__global__ __launch_bounds__(128) void ema_pass2(
    const float* __restrict__ x,
    const float* __restrict__ h_a0,
    const float* __restrict__ h_sd0,
    const float* __restrict__ alpha,
    float* __restrict__ out,
    int write_tail)
{
    const int c = blockIdx.x;            // 0..CR-1 (fast axis, as in r12)
    const int g = blockIdx.y;            // 0..15
    const int d = threadIdx.x;           // 0..127

    const int n0 = g, n1 = g + 16;
    const int i0 = n0 * DD + d, i1 = n1 * DD + d;

    const float a0 = alpha[i0], a1 = alpha[i1];
    const float b0 = 1.0f - a0, b1 = 1.0f - a1;

    // per-lane fold constants: W = b^64
    float W0, W1;
    {
        float p = b0 * b0; p *= p; p *= p; p *= p; p *= p; W0 = p * p;
    }
    {
        float p = b1 * b1; p *= p; p *= p; p *= p; p *= p; W1 = p * p;
    }
    const float Cq0 = W0 * (1.0f - W0), Cq1 = W1 * (1.0f - W1);
    const float m2W0 = -2.0f * W0,      m2W1 = -2.0f * W1;

    float ha0 = h_a0[i0], ha1 = h_a0[i1];
    float sd;
    sd = h_sd0[i0]; float hv0 = sd * sd;
    sd = h_sd0[i1]; float hv1 = sd * sd;

    // entry state: fold summaries 0 .. 2c-1 (LS=64 granularity)
    const int nfold = 2 * c;
#pragma unroll 4
    for (int cc = 0; cc < nfold; ++cc) {
        const int sb = cc * LANES;
        const float P0 = g_P[sb + i0], Aa0 = g_A[sb + i0];
        const float P1 = g_P[sb + i1], Aa1 = g_A[sb + i1];
        float hvn;
        hvn = fmaf(W0, hv0, fmaf(Cq0, ha0 * ha0, fmaf(m2W0 * P0, ha0, Aa0)));
        hv0 = fmaxf(hvn, 0.f);
        ha0 = fmaf(W0, ha0, P0);
        hvn = fmaf(W1, hv1, fmaf(Cq1, ha1 * ha1, fmaf(m2W1 * P1, ha1, Aa1)));
        hv1 = fmaxf(hvn, 0.f);
        ha1 = fmaf(W1, ha1, P1);
    }

    // exact replay with scalar streaming stores (one x load feeds 2 lanes)
    const float* xp = x + (size_t)c * LR * DD + d;
    float* obase = out + (size_t)c * LR * (2 * NN * DD);

#pragma unroll 8
    for (int i = 0; i < LR; ++i) {
        const float xv = xp[(size_t)i * DD];
        float u;
        u = xv - ha0; ha0 = fmaf(a0, u, ha0); hv0 = b0 * fmaf(a0, u * u, hv0);
        u = xv - ha1; ha1 = fmaf(a1, u, ha1); hv1 = b1 * fmaf(a1, u * u, hv1);
        float* op = obase + (size_t)i * (2 * NN * DD);
        __stcs(op + i0, ha0);
        __stcs(op + NN * DD + i0, sqrt_fast(hv0));
        __stcs(op + i1, ha1);
        __stcs(op + NN * DD + i1, sqrt_fast(hv1));
    }

    // tail: final states from the last chunk's replay-exit state
    if (write_tail && c == CR - 1) {
        const size_t base = (size_t)TT * 2 * NN * DD;
        out[base + i0] = ha0;
        out[base + LANES + i0] = sqrt_fast(hv0);
        out[base + i1] = ha1;
        out[base + LANES + i1] = sqrt_fast(hv1);
    }
}

extern "C" void kernel_launch(void* const* d_in, const int* in_sizes, int n_in,
                              void* d_out, int out_size)
{
    const float* x     = (const float*)d_in[0];
    const float* h_a0  = (const float*)d_in[1];
    const float* h_sd0 = (const float*)d_in[2];
    const float* alpha = (const float*)d_in[3];
    float* out = (float*)d_out;

    const int main_elems = TT * 2 * NN * DD;
    const int write_tail = (out_size > main_elems) ? 1 : 0;

    dim3 grid1(CS, 8);
    ema_pass1<<<grid1, 128>>>(x, alpha);
    dim3 grid2(CR, 16);
    ema_pass2<<<grid2, 128>>>(x, h_a0, h_sd0, alpha, out, write_tail);
}

// round 17
// speedup vs baseline: 1.0897x; 1.0897x over previous
#include <cuda_runtime.h>
#include <cuda_bf16.h>
#include <math.h>

// EMA with SD, chunked parallel scan (round 17).
// x (T=8192, D=128); h_a0, h_sd0, alpha (N=32, D=128).
// out: (T, 2N, D) fp32, then hN_a (N,D), hN_sd (N,D).
//
// Recombination of the two measured-best halves:
// pass1 (r15's x-shared form): thread = (d, 4 n's), grid (CS=128, 8) x 128.
//   One x load feeds 4 state lanes (x L2 traffic 128->32MB). Exact 64-step
//   summary per lane:  u = x - g; g += a*u; A = b*(A + a*u^2).
// pass2 (r12's winner, byte-identical): CR=64 x LR=128, float2 lanes,
//   64-thr blocks (4096 warps), per-block prefix fold of summaries 0..2c-1
//   (W = b^64):
//     hv' = W*hv + W(1-W)*ha^2 - 2W*P*ha + A ; ha' = W*ha + P
//   then exact replay with __stcs float2 streaming stores + sqrt.approx.
//   c = CR-1 blocks emit hN_a / hN_sd from their replay-exit state.

#define TT 8192
#define DD 128
#define NN 32
#define CS 128
#define LS 64
#define CR 64
#define LR 128
#define LANES (NN * DD)

__device__ float g_P[CS * LANES];
__device__ float g_A[CS * LANES];

__device__ __forceinline__ float sqrt_fast(float v) {
    float r;
    asm("sqrt.approx.f32 %0, %1;" : "=f"(r) : "f"(v));
    return r;
}

// ---------------------------------------------------------------- pass 1
// Block (c, g): 128 threads = d; each thread handles n = g, g+8, g+16, g+24.
__global__ __launch_bounds__(128) void ema_pass1(
    const float* __restrict__ x,
    const float* __restrict__ alpha)
{
    const int c = blockIdx.x;            // 0..CS-1
    const int g = blockIdx.y;            // 0..7
    const int d = threadIdx.x;           // 0..127

    const int n0 = g,      n1 = g + 8,  n2 = g + 16, n3 = g + 24;
    const int i0 = n0 * DD + d, i1 = n1 * DD + d, i2 = n2 * DD + d, i3 = n3 * DD + d;

    const float a0 = alpha[i0], a1 = alpha[i1], a2 = alpha[i2], a3 = alpha[i3];
    const float b0 = 1.0f - a0, b1 = 1.0f - a1, b2 = 1.0f - a2, b3 = 1.0f - a3;

    const float* xp = x + (size_t)c * LS * DD + d;

    float g0 = 0.f, g1 = 0.f, g2 = 0.f, g3 = 0.f;
    float A0 = 0.f, A1 = 0.f, A2 = 0.f, A3 = 0.f;

#pragma unroll 8
    for (int i = 0; i < LS; ++i) {
        const float xv = xp[(size_t)i * DD];   // one load feeds 4 lanes
        float u;
        u = xv - g0; g0 = fmaf(a0, u, g0); A0 = b0 * fmaf(a0, u * u, A0);
        u = xv - g1; g1 = fmaf(a1, u, g1); A1 = b1 * fmaf(a1, u * u, A1);
        u = xv - g2; g2 = fmaf(a2, u, g2); A2 = b2 * fmaf(a2, u * u, A2);
        u = xv - g3; g3 = fmaf(a3, u, g3); A3 = b3 * fmaf(a3, u * u, A3);
    }

    const int sbase = c * LANES;
    g_P[sbase + i0] = g0;  g_A[sbase + i0] = A0;
    g_P[sbase + i1] = g1;  g_A[sbase + i1] = A1;
    g_P[sbase + i2] = g2;  g_A[sbase + i2] = A2;
    g_P[sbase + i3] = g3;  g_A[sbase + i3] = A3;
}

// ---------------------------------------------------------------- pass 2
// (byte-identical to round-12's winner)
__global__ __launch_bounds__(64) void ema_pass2(
    const float* __restrict__ x,
    const float* __restrict__ h_a0,
    const float* __restrict__ h_sd0,
    const float* __restrict__ alpha,
    float* __restrict__ out,
    int write_tail)
{
    const int c  = blockIdx.x;           // 0..CR-1
    const int n  = blockIdx.y;           // 0..NN-1
    const int d2 = threadIdx.x;          // 0..63
    const int idx = n * DD + 2 * d2;

    const float2 al = *reinterpret_cast<const float2*>(alpha + idx);
    const float a0 = al.x, a1 = al.y;
    const float b0 = 1.0f - a0, b1 = 1.0f - a1;

    // per-lane fold constants: W = b^64
    float W0, W1;
    {
        float p = b0 * b0; p *= p; p *= p; p *= p; p *= p; W0 = p * p;
    }
    {
        float p = b1 * b1; p *= p; p *= p; p *= p; p *= p; W1 = p * p;
    }
    const float Cq0 = W0 * (1.0f - W0), Cq1 = W1 * (1.0f - W1);
    const float m2W0 = -2.0f * W0,      m2W1 = -2.0f * W1;

    // entry state: fold summaries 0 .. 2c-1 (LS=64 granularity)
    const float2 hav = *reinterpret_cast<const float2*>(h_a0 + idx);
    const float2 sdv = *reinterpret_cast<const float2*>(h_sd0 + idx);
    float ha0 = hav.x, ha1 = hav.y;
    float hv0 = sdv.x * sdv.x, hv1 = sdv.y * sdv.y;

    const int nfold = 2 * c;
#pragma unroll 4
    for (int cc = 0; cc < nfold; ++cc) {
        const int s = cc * LANES + idx;
        const float2 P  = *reinterpret_cast<const float2*>(g_P + s);
        const float2 Aa = *reinterpret_cast<const float2*>(g_A + s);
        float hvn;
        hvn = fmaf(W0, hv0, fmaf(Cq0, ha0 * ha0, fmaf(m2W0 * P.x, ha0, Aa.x)));
        hv0 = fmaxf(hvn, 0.f);
        ha0 = fmaf(W0, ha0, P.x);
        hvn = fmaf(W1, hv1, fmaf(Cq1, ha1 * ha1, fmaf(m2W1 * P.y, ha1, Aa.y)));
        hv1 = fmaxf(hvn, 0.f);
        ha1 = fmaf(W1, ha1, P.y);
    }

    // exact replay with streaming stores
    const float2* xp = reinterpret_cast<const float2*>(x + (size_t)c * LR * DD + 2 * d2);
    float2* obase = reinterpret_cast<float2*>(out + (size_t)c * LR * 2 * NN * DD + n * DD + 2 * d2);

#pragma unroll 8
    for (int i = 0; i < LR; ++i) {
        const float2 xv = xp[(size_t)i * (DD / 2)];
        const float u0 = xv.x - ha0;
        const float u1 = xv.y - ha1;
        ha0 = fmaf(a0, u0, ha0);
        ha1 = fmaf(a1, u1, ha1);
        hv0 = b0 * fmaf(a0, u0 * u0, hv0);
        hv1 = b1 * fmaf(a1, u1 * u1, hv1);
        float2* op = obase + (size_t)i * (NN * DD);      // i * 4096 float2
        __stcs(op, make_float2(ha0, ha1));
        __stcs(op + (NN * DD / 2), make_float2(sqrt_fast(hv0), sqrt_fast(hv1)));
    }

    // tail: final states from the last chunk's replay-exit state
    if (write_tail && c == CR - 1) {
        const size_t base = (size_t)TT * 2 * NN * DD;
        *reinterpret_cast<float2*>(out + base + idx) = make_float2(ha0, ha1);
        *reinterpret_cast<float2*>(out + base + LANES + idx) =
            make_float2(sqrt_fast(hv0), sqrt_fast(hv1));
    }
}

extern "C" void kernel_launch(void* const* d_in, const int* in_sizes, int n_in,
                              void* d_out, int out_size)
{
    const float* x     = (const float*)d_in[0];
    const float* h_a0  = (const float*)d_in[1];
    const float* h_sd0 = (const float*)d_in[2];
    const float* alpha = (const float*)d_in[3];
    float* out = (float*)d_out;

    const int main_elems = TT * 2 * NN * DD;
    const int write_tail = (out_size > main_elems) ? 1 : 0;

    dim3 grid1(CS, 8);
    ema_pass1<<<grid1, 128>>>(x, alpha);
    dim3 grid2(CR, NN);
    ema_pass2<<<grid2, 64>>>(x, h_a0, h_sd0, alpha, out, write_tail);
}